// round 6
// baseline (speedup 1.0000x reference)
#include <cuda_runtime.h>
#include <cuda_fp16.h>
#include <math.h>
#include <stdint.h>

#define B_    8192
#define T_    20
#define MBT   163840        // B_*T_
#define NF    812
#define HID   400
#define G4    1600
#define NP    1664          // padded interleaved gate width (416 h-units * 4)
#define VAR   811
#define LDW   813           // W_ih row stride in input

#define KPB   832           // padded K, big GEMM (26*32)
#define KPR   416           // padded K, recurrent GEMM (13*32)

#define BM    128
#define BN    128
#define BK    32
#define STAGES 4
#define STAGE_BYTES 16384   // A 8KB + B 8KB
#define SMEM_DYN (STAGES * STAGE_BYTES)   // 64KB
#define SROW  136           // staging row stride in halves (128 + 8 pad)

// ---------------- device scratch ------------------------------------------------
// interleaved gate layout everywhere: col = 4*h + q, q in {i,f,g,o}
__device__ __align__(128) __half d_pre[(size_t)MBT * NP];     // ~545 MB
__device__ __align__(128) __half d_valh[(size_t)MBT * KPB];   // ~273 MB
__device__ __align__(128) __half d_wih_h[NP * KPB];
__device__ __align__(128) __half d_whh_h[NP * KPR];
__device__ __align__(128) __half d_hdec0[B_ * KPR];           // ping-pong h*gamma
__device__ __align__(128) __half d_hdec1[B_ * KPR];
__device__ float d_c[B_ * HID];
__device__ float d_xh[T_ * B_];
__device__ float d_alpha[B_];
__device__ float d_mm[B_];
__device__ float d_wsum[HID];
__device__ float d_wvi[NP];
__device__ float d_wmi[NP];
__device__ float d_bsumi[NP];
__device__ float d_steploss[T_];

// ---------------- portable PTX helpers -------------------------------------------
__device__ __forceinline__ void cp16(uint32_t saddr, const void* g) {
    asm volatile("cp.async.cg.shared.global [%0], [%1], 16;" :: "r"(saddr), "l"(g));
}
__device__ __forceinline__ void cp_commit() {
    asm volatile("cp.async.commit_group;" ::: "memory");
}
template <int N>
__device__ __forceinline__ void cp_wait() {
    asm volatile("cp.async.wait_group %0;" :: "n"(N) : "memory");
}
__device__ __forceinline__ void ldm_x4(uint32_t* r, uint32_t addr) {
    asm volatile("ldmatrix.sync.aligned.m8n8.x4.shared.b16 {%0,%1,%2,%3}, [%4];"
                 : "=r"(r[0]), "=r"(r[1]), "=r"(r[2]), "=r"(r[3]) : "r"(addr));
}
__device__ __forceinline__ void mma16816(float* c, const uint32_t* a, const uint32_t* b) {
    asm volatile(
        "mma.sync.aligned.m16n8k16.row.col.f32.f16.f16.f32 "
        "{%0,%1,%2,%3}, {%4,%5,%6,%7}, {%8,%9}, {%0,%1,%2,%3};"
        : "+f"(c[0]), "+f"(c[1]), "+f"(c[2]), "+f"(c[3])
        : "r"(a[0]), "r"(a[1]), "r"(a[2]), "r"(a[3]), "r"(b[0]), "r"(b[1]));
}
__device__ __forceinline__ uint32_t swz(uint32_t off) {   // 64B-row swizzle
    return off ^ ((off >> 3) & 0x30);
}
__device__ __forceinline__ float sigf(float x) { return 1.f / (1.f + expf(-x)); }

// ---------------- HMMA GEMM: C = A[M,K] @ Bw[NP,K]^T ------------------------------
// FUSED=false: write fp16 C (stride NP) to Cout.
// FUSED=true : recurrent step t. smem-stage the tile, then per-row LSTM pointwise:
//              gates += pre + bias + alpha*wv + m*wm; update d_c; write
//              h*gamma(t+1) (fp16) to Cout (= hdec ping buffer, stride KPR).
template <bool FUSED>
__global__ __launch_bounds__(256, 2)
void gemm_hmma(const __half* __restrict__ A, const __half* __restrict__ Bw,
               int ldA, int ldB, int NK, __half* __restrict__ Cout,
               int t, const float* __restrict__ deltas,
               const float* __restrict__ b_decay)
{
    extern __shared__ __align__(128) char sm[];
    const uint32_t smbase = (uint32_t)__cvta_generic_to_shared(sm);

    const int tid  = threadIdx.x;
    const int lane = tid & 31;
    const int wid  = tid >> 5;
    const int wm0  = (wid >> 2) * 64;
    const int wn0  = (wid & 3) * 32;
    const int m0   = blockIdx.y * BM;
    const int n0   = blockIdx.x * BN;

    const int ldRow0 = tid >> 2,         ldCh0 = tid & 3;
    const int ldRow1 = (tid + 256) >> 2, ldCh1 = (tid + 256) & 3;

    float acc[4][4][4] = {};

    auto load_stage = [&](int s, int kt) {
        uint32_t aB = smbase + s * STAGE_BYTES;
        uint32_t bB = aB + 8192;
        cp16(aB + swz(ldRow0 * 64 + ldCh0 * 16), A + (size_t)(m0 + ldRow0) * ldA + kt * BK + ldCh0 * 8);
        cp16(aB + swz(ldRow1 * 64 + ldCh1 * 16), A + (size_t)(m0 + ldRow1) * ldA + kt * BK + ldCh1 * 8);
        cp16(bB + swz(ldRow0 * 64 + ldCh0 * 16), Bw + (size_t)(n0 + ldRow0) * ldB + kt * BK + ldCh0 * 8);
        cp16(bB + swz(ldRow1 * 64 + ldCh1 * 16), Bw + (size_t)(n0 + ldRow1) * ldB + kt * BK + ldCh1 * 8);
    };

    #pragma unroll
    for (int s = 0; s < 3; s++) {
        if (s < NK) load_stage(s, s);
        cp_commit();
    }

    const int aRow = lane & 15, aChk = lane >> 4;
    const int bG   = lane >> 3, bR   = lane & 7;

    for (int kt = 0; kt < NK; kt++) {
        cp_wait<2>();
        __syncthreads();
        if (kt + 3 < NK) load_stage((kt + 3) % STAGES, kt + 3);
        cp_commit();

        uint32_t aB = smbase + (kt % STAGES) * STAGE_BYTES;
        uint32_t bB = aB + 8192;

        #pragma unroll
        for (int ks = 0; ks < 2; ks++) {
            uint32_t afr[4][4];
            #pragma unroll
            for (int mt = 0; mt < 4; mt++) {
                int row = wm0 + mt * 16 + aRow;
                ldm_x4(afr[mt], aB + swz(row * 64 + (ks * 2 + aChk) * 16));
            }
            uint32_t bfr[4][2];
            #pragma unroll
            for (int p = 0; p < 2; p++) {
                uint32_t r[4];
                int nt    = p * 2 + (bG >> 1);
                int chunk = ks * 2 + (bG & 1);
                int row   = wn0 + nt * 8 + bR;
                ldm_x4(r, bB + swz(row * 64 + chunk * 16));
                bfr[p * 2][0] = r[0]; bfr[p * 2][1] = r[1];
                bfr[p * 2 + 1][0] = r[2]; bfr[p * 2 + 1][1] = r[3];
            }
            #pragma unroll
            for (int mt = 0; mt < 4; mt++)
                #pragma unroll
                for (int nt = 0; nt < 4; nt++)
                    mma16816(acc[mt][nt], afr[mt], bfr[nt]);
        }
    }

    if (!FUSED) {
        #pragma unroll
        for (int mt = 0; mt < 4; mt++) {
            int r0 = m0 + wm0 + mt * 16 + (lane >> 2);
            #pragma unroll
            for (int nt = 0; nt < 4; nt++) {
                int c = n0 + wn0 + nt * 8 + 2 * (lane & 3);
                *(__half2*)(Cout + (size_t)r0 * NP + c) =
                    __float22half2_rn(make_float2(acc[mt][nt][0], acc[mt][nt][1]));
                *(__half2*)(Cout + (size_t)(r0 + 8) * NP + c) =
                    __float22half2_rn(make_float2(acc[mt][nt][2], acc[mt][nt][3]));
            }
        }
    } else {
        // ---- stage accumulators to smem (fp16) ----
        __syncthreads();   // all warps done reading pipeline stages
        #pragma unroll
        for (int mt = 0; mt < 4; mt++) {
            int rl0 = wm0 + mt * 16 + (lane >> 2);
            #pragma unroll
            for (int nt = 0; nt < 4; nt++) {
                int cl = wn0 + nt * 8 + 2 * (lane & 3);
                *(__half2*)(sm + (rl0 * SROW + cl) * 2) =
                    __float22half2_rn(make_float2(acc[mt][nt][0], acc[mt][nt][1]));
                *(__half2*)(sm + ((rl0 + 8) * SROW + cl) * 2) =
                    __float22half2_rn(make_float2(acc[mt][nt][2], acc[mt][nt][3]));
            }
        }
        __syncthreads();

        // ---- coalesced pointwise: 2 threads per row, 16 quads each ----
        const int rl = tid >> 1;              // local row 0..127
        const int sq = tid & 1;               // which 16-quad half
        const int r  = m0 + rl;               // global sample
        const float alpha = d_alpha[r];
        const float mv    = d_mm[r];
        const float dlt1  = deltas[r * T_ + t + 1];
        const __half* prerow = d_pre + ((size_t)r * T_ + t) * NP;
        float*  crow  = d_c + (size_t)r * HID;
        __half* hdrow = Cout + (size_t)r * KPR;

        #pragma unroll 4
        for (int i = 0; i < 16; i++) {
            const int qi  = sq * 16 + i;
            const int col = n0 + qi * 4;
            const int h   = col >> 2;
            if (h >= HID) break;
            uint2 gw = *(const uint2*)(sm + (rl * SROW + qi * 4) * 2);
            float2 g01 = __half22float2(*(const __half2*)&gw.x);
            float2 g23 = __half22float2(*(const __half2*)&gw.y);
            float2 p01 = __half22float2(*(const __half2*)(prerow + col));
            float2 p23 = __half22float2(*(const __half2*)(prerow + col + 2));
            float4 bs = *(const float4*)(d_bsumi + col);
            float4 wv = *(const float4*)(d_wvi + col);
            float4 wm = *(const float4*)(d_wmi + col);
            float gi_ = g01.x + p01.x + bs.x + alpha * wv.x + mv * wm.x;
            float gf_ = g01.y + p01.y + bs.y + alpha * wv.y + mv * wm.y;
            float gg_ = g23.x + p23.x + bs.z + alpha * wv.z + mv * wm.z;
            float go_ = g23.y + p23.y + bs.w + alpha * wv.w + mv * wm.w;
            float cn  = sigf(gf_) * crow[h] + sigf(gi_) * tanhf(gg_);
            crow[h] = cn;
            float hv  = sigf(go_) * tanhf(cn);
            float z   = dlt1 * d_wsum[h] + b_decay[h];
            float gamma = expf(-fmaxf(z, 0.f));
            hdrow[h] = __float2half_rn(hv * gamma);
        }
    }
}

// ---------------- x_h reduction: warp per sample ------------------------------------
__global__ void xh_kernel(int t1, const __half* __restrict__ hdec,
                          const float* __restrict__ values,
                          const float* __restrict__ masks,
                          const float* __restrict__ W_reg,
                          const float* __restrict__ b_reg)
{
    const int w    = (blockIdx.x * blockDim.x + threadIdx.x) >> 5;
    const int lane = threadIdx.x & 31;
    if (w >= B_) return;
    float p = 0.f;
    for (int k = lane; k < HID; k += 32)
        p += __half2float(hdec[(size_t)w * KPR + k]) * W_reg[k];
    #pragma unroll
    for (int s = 16; s > 0; s >>= 1)
        p += __shfl_xor_sync(0xffffffffu, p, s);
    if (lane == 0) {
        float xh = p + b_reg[0];
        d_xh[t1 * B_ + w] = xh;
        float m  = masks[w * T_ + t1];
        float xr = values[((size_t)w * T_ + t1) * NF + VAR];
        d_alpha[w] = (1.f - m) * (xh - xr);
        d_mm[w]    = m;
    }
}

// ---------------- conversions / prep ------------------------------------------------
__global__ void conv_values_kernel(const float* __restrict__ values)
{
    const int row = blockIdx.x;
    const int c4  = threadIdx.x;          // float4 index within row
    if (c4 >= KPB / 4) return;
    __half2 h0, h1;
    if (c4 < NF / 4) {                    // NF/4 = 203 exact
        float4 v = *(const float4*)(values + (size_t)row * NF + c4 * 4);
        h0 = __float22half2_rn(make_float2(v.x, v.y));
        h1 = __float22half2_rn(make_float2(v.z, v.w));
    } else {
        h0 = __half2(__float2half(0.f), __float2half(0.f));
        h1 = h0;
    }
    __half2* dst = (__half2*)(d_valh + (size_t)row * KPB + c4 * 4);
    dst[0] = h0;
    dst[1] = h1;
}

__global__ void prep_kernel(const float* __restrict__ W_decay,
                            const float* __restrict__ W_ih,
                            const float* __restrict__ W_hh,
                            const float* __restrict__ b_ih,
                            const float* __restrict__ b_hh,
                            const float* __restrict__ values,
                            const float* __restrict__ masks,
                            const float* __restrict__ b_reg)
{
    int idx = blockIdx.x * blockDim.x + threadIdx.x;
    int stride = gridDim.x * blockDim.x;

    for (int i = idx; i < NP * KPB; i += stride) {
        int col = i / KPB, k = i - col * KPB;
        int h = col >> 2, q = col & 3;
        d_wih_h[i] = (h < HID && k < NF)
                   ? __float2half_rn(W_ih[(size_t)(q * HID + h) * LDW + k]) : __half(0.f);
    }
    for (int i = idx; i < NP * KPR; i += stride) {
        int col = i / KPR, k = i - col * KPR;
        int h = col >> 2, q = col & 3;
        d_whh_h[i] = (h < HID && k < HID)
                   ? __float2half_rn(W_hh[(size_t)(q * HID + h) * HID + k]) : __half(0.f);
    }
    for (int i = idx; i < NP; i += stride) {
        int h = i >> 2, q = i & 3;
        if (h < HID) {
            int r = q * HID + h;
            d_wvi[i]   = W_ih[(size_t)r * LDW + VAR];
            d_wmi[i]   = W_ih[(size_t)r * LDW + NF];
            d_bsumi[i] = b_ih[r] + b_hh[r];
        } else {
            d_wvi[i] = 0.f; d_wmi[i] = 0.f; d_bsumi[i] = 0.f;
        }
    }
    for (int i = idx; i < HID; i += stride) {
        float s = 0.f;
        const float* row = W_decay + (size_t)i * NF;
        for (int k = 0; k < NF; k++) s += row[k];
        d_wsum[i] = s;
    }
    for (int i = idx; i < B_ * HID; i += stride) d_c[i] = 0.f;
    for (int i = idx; i < B_ * KPR; i += stride) {
        d_hdec0[i] = __half(0.f);
        d_hdec1[i] = __half(0.f);
    }
    for (int i = idx; i < B_; i += stride) {
        float xh0 = b_reg[0];                  // h0 = 0 -> x_h = b_reg
        float m0  = masks[i * T_];
        float xr0 = values[(size_t)i * T_ * NF + VAR];
        d_xh[i]    = xh0;
        d_alpha[i] = (1.f - m0) * (xh0 - xr0);
        d_mm[i]    = m0;
    }
}

// ---------------- loss + writeout ------------------------------------------------------
__global__ void loss_kernel(const float* __restrict__ values,
                            const float* __restrict__ masks)
{
    __shared__ float snum[256];
    __shared__ float sden[256];
    const int t = blockIdx.x;
    float num = 0.f, den = 0.f;
    for (int b = threadIdx.x; b < B_; b += 256) {
        float m  = masks[b * T_ + t];
        float xr = values[(size_t)(b * T_ + t) * NF + VAR];
        float xh = d_xh[t * B_ + b];
        num += m * fabsf(xr - xh);
        den += m;
    }
    snum[threadIdx.x] = num;
    sden[threadIdx.x] = den;
    __syncthreads();
    for (int s = 128; s > 0; s >>= 1) {
        if (threadIdx.x < s) {
            snum[threadIdx.x] += snum[threadIdx.x + s];
            sden[threadIdx.x] += sden[threadIdx.x + s];
        }
        __syncthreads();
    }
    if (threadIdx.x == 0) d_steploss[t] = snum[0] / (sden[0] + 1e-5f);
}

__global__ void writeout_kernel(const float* __restrict__ values,
                                const float* __restrict__ masks,
                                float* __restrict__ out, int out_size)
{
    int idx = blockIdx.x * blockDim.x + threadIdx.x;   // over B*T
    const int has_loss = (out_size > B_ * T_) ? 1 : 0;
    if (idx < B_ * T_) {
        int b = idx / T_, t = idx - b * T_;
        float m   = masks[idx];
        float xr  = values[(size_t)idx * NF + VAR];
        float xh  = d_xh[t * B_ + b];
        float imp = m * xr + (1.f - m) * xh;
        int o = has_loss + idx;
        if (o < out_size) out[o] = imp;
    }
    if (idx == 0 && has_loss) {
        float s = 0.f;
        for (int t = 0; t < T_; t++) s += d_steploss[t];
        out[0] = s / (float)T_;
    }
}

// ---------------- launch -----------------------------------------------------------------
extern "C" void kernel_launch(void* const* d_in, const int* in_sizes, int n_in,
                              void* d_out, int out_size)
{
    const float* values  = (const float*)d_in[0];
    const float* masks   = (const float*)d_in[1];
    const float* deltas  = (const float*)d_in[2];
    const float* W_decay = (const float*)d_in[3];
    const float* b_decay = (const float*)d_in[4];
    const float* W_reg   = (const float*)d_in[5];
    const float* b_reg   = (const float*)d_in[6];
    const float* W_ih    = (const float*)d_in[7];
    const float* W_hh    = (const float*)d_in[8];
    const float* b_ih    = (const float*)d_in[9];
    const float* b_hh    = (const float*)d_in[10];
    float* out = (float*)d_out;

    __half *pre_p, *valh_p, *wih_p, *whh_p, *hd0_p, *hd1_p;
    cudaGetSymbolAddress((void**)&pre_p,  d_pre);
    cudaGetSymbolAddress((void**)&valh_p, d_valh);
    cudaGetSymbolAddress((void**)&wih_p,  d_wih_h);
    cudaGetSymbolAddress((void**)&whh_p,  d_whh_h);
    cudaGetSymbolAddress((void**)&hd0_p,  d_hdec0);
    cudaGetSymbolAddress((void**)&hd1_p,  d_hdec1);
    __half* hd[2] = {hd0_p, hd1_p};

    cudaFuncSetAttribute(gemm_hmma<false>, cudaFuncAttributeMaxDynamicSharedMemorySize, SMEM_DYN);
    cudaFuncSetAttribute(gemm_hmma<true>,  cudaFuncAttributeMaxDynamicSharedMemorySize, SMEM_DYN);

    conv_values_kernel<<<MBT, 256>>>(values);
    prep_kernel<<<4096, 256>>>(W_decay, W_ih, W_hh, b_ih, b_hh, values, masks, b_reg);

    // pre[MBT, NP] = valh @ wih_h^T   (K = 832 -> 26 k-tiles), fp16 out, interleaved cols
    {
        dim3 grid(NP / BN, MBT / BM);
        gemm_hmma<false><<<grid, 256, SMEM_DYN>>>(valh_p, wih_p, KPB, KPB, KPB / BK,
                                                  pre_p, 0, deltas, b_decay);
    }

    // recurrence: last step (t = T-1) is dead code for the outputs -> 19 iterations
    for (int t = 0; t < T_ - 1; t++) {
        dim3 grid(NP / BN, B_ / BM);
        gemm_hmma<true><<<grid, 256, SMEM_DYN>>>(hd[t & 1], whh_p, KPR, KPR, KPR / BK,
                                                 hd[(t + 1) & 1], t, deltas, b_decay);
        xh_kernel<<<B_ * 32 / 256, 256>>>(t + 1, hd[(t + 1) & 1], values, masks, W_reg, b_reg);
    }

    loss_kernel<<<T_, 256>>>(values, masks);
    writeout_kernel<<<(B_ * T_ + 255) / 256, 256>>>(values, masks, out, out_size);
}

// round 10
// speedup vs baseline: 1.0087x; 1.0087x over previous
#include <cuda_runtime.h>
#include <cuda_fp16.h>
#include <math.h>
#include <stdint.h>

#define B_    8192
#define T_    20
#define MBT   163840        // B_*T_
#define NF    812
#define HID   400
#define G4    1600
#define NP    1664          // padded interleaved gate width (416 h-units * 4)
#define VAR   811
#define LDW   813           // W_ih row stride in input

#define KPB   832           // padded K, big GEMM (26*32)
#define KPR   416           // padded K, recurrent GEMM (13*32)

#define BM    128
#define BN    128
#define BK    32
#define STAGES 4
#define STAGE_BYTES 16384   // A 8KB + B 8KB
#define SMEM_DYN (STAGES * STAGE_BYTES)   // 64KB
#define SROW  136           // staging row stride in halves (128 + 8 pad)

// ---------------- device scratch ------------------------------------------------
// interleaved gate layout everywhere: col = 4*h + q, q in {i,f,g,o}
__device__ __align__(128) __half d_pre[(size_t)MBT * NP];     // ~545 MB
__device__ __align__(128) __half d_valh[(size_t)MBT * KPB];   // ~273 MB
__device__ __align__(128) __half d_wih_h[NP * KPB];
__device__ __align__(128) __half d_whh_h[NP * KPR];
__device__ __align__(128) __half d_hdec0[B_ * KPR];           // ping-pong h*gamma
__device__ __align__(128) __half d_hdec1[B_ * KPR];
__device__ float d_c[B_ * HID];
__device__ float d_xh[T_ * B_];
__device__ float d_alpha[B_];
__device__ float d_mm[B_];
__device__ float d_wsum[HID];
__device__ float d_wvi[NP];
__device__ float d_wmi[NP];
__device__ float d_bsumi[NP];
__device__ float d_steploss[T_];

// ---------------- portable PTX helpers -------------------------------------------
__device__ __forceinline__ void cp16(uint32_t saddr, const void* g) {
    asm volatile("cp.async.cg.shared.global [%0], [%1], 16;" :: "r"(saddr), "l"(g));
}
__device__ __forceinline__ void cp_commit() {
    asm volatile("cp.async.commit_group;" ::: "memory");
}
template <int N>
__device__ __forceinline__ void cp_wait() {
    asm volatile("cp.async.wait_group %0;" :: "n"(N) : "memory");
}
__device__ __forceinline__ void ldm_x4(uint32_t* r, uint32_t addr) {
    asm volatile("ldmatrix.sync.aligned.m8n8.x4.shared.b16 {%0,%1,%2,%3}, [%4];"
                 : "=r"(r[0]), "=r"(r[1]), "=r"(r[2]), "=r"(r[3]) : "r"(addr));
}
__device__ __forceinline__ void mma16816(float* c, const uint32_t* a, const uint32_t* b) {
    asm volatile(
        "mma.sync.aligned.m16n8k16.row.col.f32.f16.f16.f32 "
        "{%0,%1,%2,%3}, {%4,%5,%6,%7}, {%8,%9}, {%0,%1,%2,%3};"
        : "+f"(c[0]), "+f"(c[1]), "+f"(c[2]), "+f"(c[3])
        : "r"(a[0]), "r"(a[1]), "r"(a[2]), "r"(a[3]), "r"(b[0]), "r"(b[1]));
}
__device__ __forceinline__ uint32_t swz(uint32_t off) {   // 64B-row swizzle
    return off ^ ((off >> 3) & 0x30);
}
__device__ __forceinline__ float sigf(float x) { return 1.f / (1.f + expf(-x)); }

// ---------------- HMMA GEMM: C = A[M,K] @ Bw[NP,K]^T ------------------------------
// FUSED=false: write fp16 C (stride NP) to Cout.
// FUSED=true : recurrent step t. smem-stage the tile, then per-row LSTM pointwise:
//              gates += pre + bias + alpha*wv + m*wm; update d_c; write
//              h*gamma(t+1) (fp16) to Cout (= hdec ping buffer, stride KPR).
template <bool FUSED>
__global__ __launch_bounds__(256, 2)
void gemm_hmma(const __half* __restrict__ A, const __half* __restrict__ Bw,
               int ldA, int ldB, int NK, __half* __restrict__ Cout,
               int t, const float* __restrict__ deltas,
               const float* __restrict__ b_decay)
{
    extern __shared__ __align__(128) char sm[];
    const uint32_t smbase = (uint32_t)__cvta_generic_to_shared(sm);

    const int tid  = threadIdx.x;
    const int lane = tid & 31;
    const int wid  = tid >> 5;
    const int wm0  = (wid >> 2) * 64;
    const int wn0  = (wid & 3) * 32;
    const int m0   = blockIdx.y * BM;
    const int n0   = blockIdx.x * BN;

    const int ldRow0 = tid >> 2,         ldCh0 = tid & 3;
    const int ldRow1 = (tid + 256) >> 2, ldCh1 = (tid + 256) & 3;

    float acc[4][4][4] = {};

    auto load_stage = [&](int s, int kt) {
        uint32_t aB = smbase + s * STAGE_BYTES;
        uint32_t bB = aB + 8192;
        cp16(aB + swz(ldRow0 * 64 + ldCh0 * 16), A + (size_t)(m0 + ldRow0) * ldA + kt * BK + ldCh0 * 8);
        cp16(aB + swz(ldRow1 * 64 + ldCh1 * 16), A + (size_t)(m0 + ldRow1) * ldA + kt * BK + ldCh1 * 8);
        cp16(bB + swz(ldRow0 * 64 + ldCh0 * 16), Bw + (size_t)(n0 + ldRow0) * ldB + kt * BK + ldCh0 * 8);
        cp16(bB + swz(ldRow1 * 64 + ldCh1 * 16), Bw + (size_t)(n0 + ldRow1) * ldB + kt * BK + ldCh1 * 8);
    };

    #pragma unroll
    for (int s = 0; s < 3; s++) {
        if (s < NK) load_stage(s, s);
        cp_commit();
    }

    const int aRow = lane & 15, aChk = lane >> 4;
    const int bG   = lane >> 3, bR   = lane & 7;

    for (int kt = 0; kt < NK; kt++) {
        cp_wait<2>();
        __syncthreads();
        if (kt + 3 < NK) load_stage((kt + 3) % STAGES, kt + 3);
        cp_commit();

        uint32_t aB = smbase + (kt % STAGES) * STAGE_BYTES;
        uint32_t bB = aB + 8192;

        #pragma unroll
        for (int ks = 0; ks < 2; ks++) {
            uint32_t afr[4][4];
            #pragma unroll
            for (int mt = 0; mt < 4; mt++) {
                int row = wm0 + mt * 16 + aRow;
                ldm_x4(afr[mt], aB + swz(row * 64 + (ks * 2 + aChk) * 16));
            }
            uint32_t bfr[4][2];
            #pragma unroll
            for (int p = 0; p < 2; p++) {
                uint32_t r[4];
                int nt    = p * 2 + (bG >> 1);
                int chunk = ks * 2 + (bG & 1);
                int row   = wn0 + nt * 8 + bR;
                ldm_x4(r, bB + swz(row * 64 + chunk * 16));
                bfr[p * 2][0] = r[0]; bfr[p * 2][1] = r[1];
                bfr[p * 2 + 1][0] = r[2]; bfr[p * 2 + 1][1] = r[3];
            }
            #pragma unroll
            for (int mt = 0; mt < 4; mt++)
                #pragma unroll
                for (int nt = 0; nt < 4; nt++)
                    mma16816(acc[mt][nt], afr[mt], bfr[nt]);
        }
    }

    if (!FUSED) {
        #pragma unroll
        for (int mt = 0; mt < 4; mt++) {
            int r0 = m0 + wm0 + mt * 16 + (lane >> 2);
            #pragma unroll
            for (int nt = 0; nt < 4; nt++) {
                int c = n0 + wn0 + nt * 8 + 2 * (lane & 3);
                *(__half2*)(Cout + (size_t)r0 * NP + c) =
                    __float22half2_rn(make_float2(acc[mt][nt][0], acc[mt][nt][1]));
                *(__half2*)(Cout + (size_t)(r0 + 8) * NP + c) =
                    __float22half2_rn(make_float2(acc[mt][nt][2], acc[mt][nt][3]));
            }
        }
    } else {
        // ---- stage accumulators to smem (fp16) ----
        __syncthreads();   // all warps done reading pipeline stages
        #pragma unroll
        for (int mt = 0; mt < 4; mt++) {
            int rl0 = wm0 + mt * 16 + (lane >> 2);
            #pragma unroll
            for (int nt = 0; nt < 4; nt++) {
                int cl = wn0 + nt * 8 + 2 * (lane & 3);
                *(__half2*)(sm + (rl0 * SROW + cl) * 2) =
                    __float22half2_rn(make_float2(acc[mt][nt][0], acc[mt][nt][1]));
                *(__half2*)(sm + ((rl0 + 8) * SROW + cl) * 2) =
                    __float22half2_rn(make_float2(acc[mt][nt][2], acc[mt][nt][3]));
            }
        }
        __syncthreads();

        // ---- coalesced pointwise: 2 threads per row, 16 quads each ----
        const int rl = tid >> 1;              // local row 0..127
        const int sq = tid & 1;               // which 16-quad half
        const int r  = m0 + rl;               // global sample
        const float alpha = d_alpha[r];
        const float mv    = d_mm[r];
        const float dlt1  = deltas[r * T_ + t + 1];
        const __half* prerow = d_pre + ((size_t)r * T_ + t) * NP;
        float*  crow  = d_c + (size_t)r * HID;
        __half* hdrow = Cout + (size_t)r * KPR;

        #pragma unroll 4
        for (int i = 0; i < 16; i++) {
            const int qi  = sq * 16 + i;
            const int col = n0 + qi * 4;
            const int h   = col >> 2;
            if (h >= HID) break;
            uint2 gw = *(const uint2*)(sm + (rl * SROW + qi * 4) * 2);
            float2 g01 = __half22float2(*(const __half2*)&gw.x);
            float2 g23 = __half22float2(*(const __half2*)&gw.y);
            float2 p01 = __half22float2(*(const __half2*)(prerow + col));
            float2 p23 = __half22float2(*(const __half2*)(prerow + col + 2));
            float4 bs = *(const float4*)(d_bsumi + col);
            float4 wv = *(const float4*)(d_wvi + col);
            float4 wm = *(const float4*)(d_wmi + col);
            float gi_ = g01.x + p01.x + bs.x + alpha * wv.x + mv * wm.x;
            float gf_ = g01.y + p01.y + bs.y + alpha * wv.y + mv * wm.y;
            float gg_ = g23.x + p23.x + bs.z + alpha * wv.z + mv * wm.z;
            float go_ = g23.y + p23.y + bs.w + alpha * wv.w + mv * wm.w;
            float cn  = sigf(gf_) * crow[h] + sigf(gi_) * tanhf(gg_);
            crow[h] = cn;
            float hv  = sigf(go_) * tanhf(cn);
            float z   = dlt1 * d_wsum[h] + b_decay[h];
            float gamma = expf(-fmaxf(z, 0.f));
            hdrow[h] = __float2half_rn(hv * gamma);
        }
    }
}

// ---------------- x_h reduction: warp per sample ------------------------------------
__global__ void xh_kernel(int t1, const __half* __restrict__ hdec,
                          const float* __restrict__ values,
                          const float* __restrict__ masks,
                          const float* __restrict__ W_reg,
                          const float* __restrict__ b_reg)
{
    const int w    = (blockIdx.x * blockDim.x + threadIdx.x) >> 5;
    const int lane = threadIdx.x & 31;
    if (w >= B_) return;
    float p = 0.f;
    for (int k = lane; k < HID; k += 32)
        p += __half2float(hdec[(size_t)w * KPR + k]) * W_reg[k];
    #pragma unroll
    for (int s = 16; s > 0; s >>= 1)
        p += __shfl_xor_sync(0xffffffffu, p, s);
    if (lane == 0) {
        float xh = p + b_reg[0];
        d_xh[t1 * B_ + w] = xh;
        float m  = masks[w * T_ + t1];
        float xr = values[((size_t)w * T_ + t1) * NF + VAR];
        d_alpha[w] = (1.f - m) * (xh - xr);
        d_mm[w]    = m;
    }
}

// ---------------- conversions / prep ------------------------------------------------
__global__ void conv_values_kernel(const float* __restrict__ values)
{
    const int row = blockIdx.x;
    const int c4  = threadIdx.x;          // float4 index within row
    if (c4 >= KPB / 4) return;
    __half2 h0, h1;
    if (c4 < NF / 4) {                    // NF/4 = 203 exact
        float4 v = *(const float4*)(values + (size_t)row * NF + c4 * 4);
        h0 = __float22half2_rn(make_float2(v.x, v.y));
        h1 = __float22half2_rn(make_float2(v.z, v.w));
    } else {
        h0 = __half2(__float2half(0.f), __float2half(0.f));
        h1 = h0;
    }
    __half2* dst = (__half2*)(d_valh + (size_t)row * KPB + c4 * 4);
    dst[0] = h0;
    dst[1] = h1;
}

__global__ void prep_kernel(const float* __restrict__ W_decay,
                            const float* __restrict__ W_ih,
                            const float* __restrict__ W_hh,
                            const float* __restrict__ b_ih,
                            const float* __restrict__ b_hh,
                            const float* __restrict__ values,
                            const float* __restrict__ masks,
                            const float* __restrict__ b_reg)
{
    int idx = blockIdx.x * blockDim.x + threadIdx.x;
    int stride = gridDim.x * blockDim.x;

    for (int i = idx; i < NP * KPB; i += stride) {
        int col = i / KPB, k = i - col * KPB;
        int h = col >> 2, q = col & 3;
        d_wih_h[i] = (h < HID && k < NF)
                   ? __float2half_rn(W_ih[(size_t)(q * HID + h) * LDW + k]) : __half(0.f);
    }
    for (int i = idx; i < NP * KPR; i += stride) {
        int col = i / KPR, k = i - col * KPR;
        int h = col >> 2, q = col & 3;
        d_whh_h[i] = (h < HID && k < HID)
                   ? __float2half_rn(W_hh[(size_t)(q * HID + h) * HID + k]) : __half(0.f);
    }
    for (int i = idx; i < NP; i += stride) {
        int h = i >> 2, q = i & 3;
        if (h < HID) {
            int r = q * HID + h;
            d_wvi[i]   = W_ih[(size_t)r * LDW + VAR];
            d_wmi[i]   = W_ih[(size_t)r * LDW + NF];
            d_bsumi[i] = b_ih[r] + b_hh[r];
        } else {
            d_wvi[i] = 0.f; d_wmi[i] = 0.f; d_bsumi[i] = 0.f;
        }
    }
    for (int i = idx; i < HID; i += stride) {
        float s = 0.f;
        const float* row = W_decay + (size_t)i * NF;
        for (int k = 0; k < NF; k++) s += row[k];
        d_wsum[i] = s;
    }
    for (int i = idx; i < B_ * HID; i += stride) d_c[i] = 0.f;
    for (int i = idx; i < B_ * KPR; i += stride) {
        d_hdec0[i] = __half(0.f);
        d_hdec1[i] = __half(0.f);
    }
    for (int i = idx; i < B_; i += stride) {
        float xh0 = b_reg[0];                  // h0 = 0 -> x_h = b_reg
        float m0  = masks[i * T_];
        float xr0 = values[(size_t)i * T_ * NF + VAR];
        d_xh[i]    = xh0;
        d_alpha[i] = (1.f - m0) * (xh0 - xr0);
        d_mm[i]    = m0;
    }
}

// ---------------- loss + writeout ------------------------------------------------------
__global__ void loss_kernel(const float* __restrict__ values,
                            const float* __restrict__ masks)
{
    __shared__ float snum[256];
    __shared__ float sden[256];
    const int t = blockIdx.x;
    float num = 0.f, den = 0.f;
    for (int b = threadIdx.x; b < B_; b += 256) {
        float m  = masks[b * T_ + t];
        float xr = values[(size_t)(b * T_ + t) * NF + VAR];
        float xh = d_xh[t * B_ + b];
        num += m * fabsf(xr - xh);
        den += m;
    }
    snum[threadIdx.x] = num;
    sden[threadIdx.x] = den;
    __syncthreads();
    for (int s = 128; s > 0; s >>= 1) {
        if (threadIdx.x < s) {
            snum[threadIdx.x] += snum[threadIdx.x + s];
            sden[threadIdx.x] += sden[threadIdx.x + s];
        }
        __syncthreads();
    }
    if (threadIdx.x == 0) d_steploss[t] = snum[0] / (sden[0] + 1e-5f);
}

__global__ void writeout_kernel(const float* __restrict__ values,
                                const float* __restrict__ masks,
                                float* __restrict__ out, int out_size)
{
    int idx = blockIdx.x * blockDim.x + threadIdx.x;   // over B*T
    const int has_loss = (out_size > B_ * T_) ? 1 : 0;
    if (idx < B_ * T_) {
        int b = idx / T_, t = idx - b * T_;
        float m   = masks[idx];
        float xr  = values[(size_t)idx * NF + VAR];
        float xh  = d_xh[t * B_ + b];
        float imp = m * xr + (1.f - m) * xh;
        int o = has_loss + idx;
        if (o < out_size) out[o] = imp;
    }
    if (idx == 0 && has_loss) {
        float s = 0.f;
        for (int t = 0; t < T_; t++) s += d_steploss[t];
        out[0] = s / (float)T_;
    }
}

// ---------------- launch -----------------------------------------------------------------
extern "C" void kernel_launch(void* const* d_in, const int* in_sizes, int n_in,
                              void* d_out, int out_size)
{
    const float* values  = (const float*)d_in[0];
    const float* masks   = (const float*)d_in[1];
    const float* deltas  = (const float*)d_in[2];
    const float* W_decay = (const float*)d_in[3];
    const float* b_decay = (const float*)d_in[4];
    const float* W_reg   = (const float*)d_in[5];
    const float* b_reg   = (const float*)d_in[6];
    const float* W_ih    = (const float*)d_in[7];
    const float* W_hh    = (const float*)d_in[8];
    const float* b_ih    = (const float*)d_in[9];
    const float* b_hh    = (const float*)d_in[10];
    float* out = (float*)d_out;

    __half *pre_p, *valh_p, *wih_p, *whh_p, *hd0_p, *hd1_p;
    cudaGetSymbolAddress((void**)&pre_p,  d_pre);
    cudaGetSymbolAddress((void**)&valh_p, d_valh);
    cudaGetSymbolAddress((void**)&wih_p,  d_wih_h);
    cudaGetSymbolAddress((void**)&whh_p,  d_whh_h);
    cudaGetSymbolAddress((void**)&hd0_p,  d_hdec0);
    cudaGetSymbolAddress((void**)&hd1_p,  d_hdec1);
    __half* hd[2] = {hd0_p, hd1_p};

    cudaFuncSetAttribute(gemm_hmma<false>, cudaFuncAttributeMaxDynamicSharedMemorySize, SMEM_DYN);
    cudaFuncSetAttribute(gemm_hmma<true>,  cudaFuncAttributeMaxDynamicSharedMemorySize, SMEM_DYN);

    conv_values_kernel<<<MBT, 256>>>(values);
    prep_kernel<<<4096, 256>>>(W_decay, W_ih, W_hh, b_ih, b_hh, values, masks, b_reg);

    // pre[MBT, NP] = valh @ wih_h^T   (K = 832 -> 26 k-tiles), fp16 out, interleaved cols
    {
        dim3 grid(NP / BN, MBT / BM);
        gemm_hmma<false><<<grid, 256, SMEM_DYN>>>(valh_p, wih_p, KPB, KPB, KPB / BK,
                                                  pre_p, 0, deltas, b_decay);
    }

    // recurrence: last step (t = T-1) is dead code for the outputs -> 19 iterations
    for (int t = 0; t < T_ - 1; t++) {
        dim3 grid(NP / BN, B_ / BM);
        gemm_hmma<true><<<grid, 256, SMEM_DYN>>>(hd[t & 1], whh_p, KPR, KPR, KPR / BK,
                                                 hd[(t + 1) & 1], t, deltas, b_decay);
        xh_kernel<<<B_ * 32 / 256, 256>>>(t + 1, hd[(t + 1) & 1], values, masks, W_reg, b_reg);
    }

    loss_kernel<<<T_, 256>>>(values, masks);
    writeout_kernel<<<(B_ * T_ + 255) / 256, 256>>>(values, masks, out, out_size);
}

// round 12
// speedup vs baseline: 1.2421x; 1.2315x over previous
#include <cuda_runtime.h>
#include <cuda_fp16.h>
#include <math.h>
#include <stdint.h>

#define B_    8192
#define T_    20
#define MBT   163840        // B_*T_
#define NF    812
#define HID   400
#define G4    1600
#define NP    1664          // padded interleaved gate width (416 h-units * 4)
#define VAR   811
#define LDW   813           // W_ih row stride in input

#define KPB   832           // padded K, big GEMM (26*32)
#define KPR   416           // padded K, recurrent GEMM (13*32)

#define BM    128
#define BN    128
#define BK    32
#define STAGES 4
#define STAGE_BYTES 16384   // A 8KB + B 8KB
#define SMEM_DYN (STAGES * STAGE_BYTES)   // 64KB

// ---------------- device scratch ------------------------------------------------
// interleaved gate layout everywhere: col = 4*h + q, q in {i,f,g,o}
__device__ __align__(128) __half d_pre[(size_t)MBT * NP];     // ~545 MB
__device__ __align__(128) __half d_gates[B_ * NP];            // 27 MB
__device__ __align__(128) __half d_valh[(size_t)MBT * KPB];   // ~273 MB
__device__ __align__(128) __half d_wih_h[NP * KPB];
__device__ __align__(128) __half d_whh_h[NP * KPR];
__device__ __align__(128) __half d_hdech[B_ * KPR];
__device__ float d_c[B_ * HID];
__device__ float d_xh[T_ * B_];
__device__ float d_alpha[B_];
__device__ float d_mm[B_];
__device__ float d_wsum[HID];
__device__ float d_wvi[NP];
__device__ float d_wmi[NP];
__device__ float d_bsumi[NP];
__device__ float d_steploss[T_];

// ---------------- portable PTX helpers -------------------------------------------
__device__ __forceinline__ void cp16(uint32_t saddr, const void* g) {
    asm volatile("cp.async.cg.shared.global [%0], [%1], 16;" :: "r"(saddr), "l"(g));
}
__device__ __forceinline__ void cp_commit() {
    asm volatile("cp.async.commit_group;" ::: "memory");
}
template <int N>
__device__ __forceinline__ void cp_wait() {
    asm volatile("cp.async.wait_group %0;" :: "n"(N) : "memory");
}
__device__ __forceinline__ void ldm_x4(uint32_t* r, uint32_t addr) {
    asm volatile("ldmatrix.sync.aligned.m8n8.x4.shared.b16 {%0,%1,%2,%3}, [%4];"
                 : "=r"(r[0]), "=r"(r[1]), "=r"(r[2]), "=r"(r[3]) : "r"(addr));
}
__device__ __forceinline__ void mma16816(float* c, const uint32_t* a, const uint32_t* b) {
    asm volatile(
        "mma.sync.aligned.m16n8k16.row.col.f32.f16.f16.f32 "
        "{%0,%1,%2,%3}, {%4,%5,%6,%7}, {%8,%9}, {%0,%1,%2,%3};"
        : "+f"(c[0]), "+f"(c[1]), "+f"(c[2]), "+f"(c[3])
        : "r"(a[0]), "r"(a[1]), "r"(a[2]), "r"(a[3]), "r"(b[0]), "r"(b[1]));
}
__device__ __forceinline__ uint32_t swz(uint32_t off) {   // 64B-row swizzle
    return off ^ ((off >> 3) & 0x30);
}
__device__ __forceinline__ float sigf(float x) { return 1.f / (1.f + expf(-x)); }

// ---------------- HMMA GEMM: C[M, NP] = A[M, K] @ Bw[NP, K]^T (fp16 out) ----------
__global__ __launch_bounds__(256, 2)
void gemm_hmma(const __half* __restrict__ A, const __half* __restrict__ Bw,
               int ldA, int ldB, int NK, __half* __restrict__ Cout)
{
    extern __shared__ __align__(128) char sm[];
    const uint32_t smbase = (uint32_t)__cvta_generic_to_shared(sm);

    const int tid  = threadIdx.x;
    const int lane = tid & 31;
    const int wid  = tid >> 5;
    const int wm0  = (wid >> 2) * 64;
    const int wn0  = (wid & 3) * 32;
    const int m0   = blockIdx.y * BM;
    const int n0   = blockIdx.x * BN;

    const int ldRow0 = tid >> 2,         ldCh0 = tid & 3;
    const int ldRow1 = (tid + 256) >> 2, ldCh1 = (tid + 256) & 3;

    float acc[4][4][4] = {};

    auto load_stage = [&](int s, int kt) {
        uint32_t aB = smbase + s * STAGE_BYTES;
        uint32_t bB = aB + 8192;
        cp16(aB + swz(ldRow0 * 64 + ldCh0 * 16), A + (size_t)(m0 + ldRow0) * ldA + kt * BK + ldCh0 * 8);
        cp16(aB + swz(ldRow1 * 64 + ldCh1 * 16), A + (size_t)(m0 + ldRow1) * ldA + kt * BK + ldCh1 * 8);
        cp16(bB + swz(ldRow0 * 64 + ldCh0 * 16), Bw + (size_t)(n0 + ldRow0) * ldB + kt * BK + ldCh0 * 8);
        cp16(bB + swz(ldRow1 * 64 + ldCh1 * 16), Bw + (size_t)(n0 + ldRow1) * ldB + kt * BK + ldCh1 * 8);
    };

    #pragma unroll
    for (int s = 0; s < 3; s++) {
        if (s < NK) load_stage(s, s);
        cp_commit();
    }

    const int aRow = lane & 15, aChk = lane >> 4;
    const int bG   = lane >> 3, bR   = lane & 7;

    for (int kt = 0; kt < NK; kt++) {
        cp_wait<2>();
        __syncthreads();
        if (kt + 3 < NK) load_stage((kt + 3) % STAGES, kt + 3);
        cp_commit();

        uint32_t aB = smbase + (kt % STAGES) * STAGE_BYTES;
        uint32_t bB = aB + 8192;

        // hoist ALL fragment loads for both ks-halves, then all 64 mma —
        // exposes only one ldmatrix latency per k-tile instead of two.
        uint32_t afr[2][4][4];
        uint32_t bfr[2][4][2];
        #pragma unroll
        for (int ks = 0; ks < 2; ks++) {
            #pragma unroll
            for (int mt = 0; mt < 4; mt++) {
                int row = wm0 + mt * 16 + aRow;
                ldm_x4(afr[ks][mt], aB + swz(row * 64 + (ks * 2 + aChk) * 16));
            }
            #pragma unroll
            for (int p = 0; p < 2; p++) {
                uint32_t r[4];
                int nt    = p * 2 + (bG >> 1);
                int chunk = ks * 2 + (bG & 1);
                int row   = wn0 + nt * 8 + bR;
                ldm_x4(r, bB + swz(row * 64 + chunk * 16));
                bfr[ks][p * 2][0] = r[0]; bfr[ks][p * 2][1] = r[1];
                bfr[ks][p * 2 + 1][0] = r[2]; bfr[ks][p * 2 + 1][1] = r[3];
            }
        }
        #pragma unroll
        for (int ks = 0; ks < 2; ks++)
            #pragma unroll
            for (int mt = 0; mt < 4; mt++)
                #pragma unroll
                for (int nt = 0; nt < 4; nt++)
                    mma16816(acc[mt][nt], afr[ks][mt], bfr[ks][nt]);
    }

    #pragma unroll
    for (int mt = 0; mt < 4; mt++) {
        int r0 = m0 + wm0 + mt * 16 + (lane >> 2);
        #pragma unroll
        for (int nt = 0; nt < 4; nt++) {
            int c = n0 + wn0 + nt * 8 + 2 * (lane & 3);
            *(__half2*)(Cout + (size_t)r0 * NP + c) =
                __float22half2_rn(make_float2(acc[mt][nt][0], acc[mt][nt][1]));
            *(__half2*)(Cout + (size_t)(r0 + 8) * NP + c) =
                __float22half2_rn(make_float2(acc[mt][nt][2], acc[mt][nt][3]));
        }
    }
}

// ---------------- fused LSTM pointwise + decay(t+1) --------------------------------
// one block per sample, 416 threads (13 warps). Reads interleaved gate quads.
__global__ __launch_bounds__(416)
void lstm_fused_kernel(int t,
                       const float* __restrict__ values,
                       const float* __restrict__ masks,
                       const float* __restrict__ deltas,
                       const float* __restrict__ b_decay,
                       const float* __restrict__ W_reg,
                       const float* __restrict__ b_reg)
{
    __shared__ float sred[13];
    const int b = blockIdx.x;
    const int h = threadIdx.x;

    float hv = 0.f;
    if (h < HID) {
        const float alpha = d_alpha[b];
        const float m     = d_mm[b];
        const __half2* gp = (const __half2*)(d_gates + (size_t)b * NP + 4 * h);
        const __half2* pp = (const __half2*)(d_pre + ((size_t)b * T_ + t) * NP + 4 * h);
        float2 g01 = __half22float2(gp[0]);
        float2 g23 = __half22float2(gp[1]);
        float2 p01 = __half22float2(pp[0]);
        float2 p23 = __half22float2(pp[1]);
        float4 bs = *(const float4*)(d_bsumi + 4 * h);
        float4 wv = *(const float4*)(d_wvi   + 4 * h);
        float4 wm = *(const float4*)(d_wmi   + 4 * h);
        float gi = g01.x + p01.x + bs.x + alpha * wv.x + m * wm.x;
        float gf = g01.y + p01.y + bs.y + alpha * wv.y + m * wm.y;
        float gg = g23.x + p23.x + bs.z + alpha * wv.z + m * wm.z;
        float go = g23.y + p23.y + bs.w + alpha * wv.w + m * wm.w;
        float cold = d_c[b * HID + h];
        float cn   = sigf(gf) * cold + sigf(gi) * tanhf(gg);
        d_c[b * HID + h] = cn;
        hv = sigf(go) * tanhf(cn);
    }

    if (t + 1 < T_) {
        float partial = 0.f;
        if (h < HID) {
            float d1    = deltas[b * T_ + t + 1];
            float z     = d1 * d_wsum[h] + b_decay[h];
            float gamma = expf(-fmaxf(z, 0.f));
            float hd    = hv * gamma;
            d_hdech[b * KPR + h] = __float2half_rn(hd);
            partial = hd * W_reg[h];
        }
        #pragma unroll
        for (int s = 16; s > 0; s >>= 1)
            partial += __shfl_xor_sync(0xffffffffu, partial, s);
        if ((h & 31) == 0) sred[h >> 5] = partial;
        __syncthreads();
        if (h == 0) {
            float xh = b_reg[0];
            #pragma unroll
            for (int w = 0; w < 13; w++) xh += sred[w];
            d_xh[(t + 1) * B_ + b] = xh;
            float m1  = masks[b * T_ + t + 1];
            float xr1 = values[((size_t)b * T_ + t + 1) * NF + VAR];
            d_alpha[b] = (1.f - m1) * (xh - xr1);
            d_mm[b]    = m1;
        }
    }
}

// ---------------- conversions / prep ------------------------------------------------
__global__ void conv_values_kernel(const float* __restrict__ values)
{
    const int row = blockIdx.x;
    const int c4  = threadIdx.x;          // float4 index within row
    if (c4 >= KPB / 4) return;
    __half2 h0, h1;
    if (c4 < NF / 4) {                    // NF/4 = 203 exact
        float4 v = *(const float4*)(values + (size_t)row * NF + c4 * 4);
        h0 = __float22half2_rn(make_float2(v.x, v.y));
        h1 = __float22half2_rn(make_float2(v.z, v.w));
    } else {
        h0 = __half2(__float2half(0.f), __float2half(0.f));
        h1 = h0;
    }
    __half2* dst = (__half2*)(d_valh + (size_t)row * KPB + c4 * 4);
    dst[0] = h0;
    dst[1] = h1;
}

__global__ void prep_kernel(const float* __restrict__ W_decay,
                            const float* __restrict__ W_ih,
                            const float* __restrict__ W_hh,
                            const float* __restrict__ b_ih,
                            const float* __restrict__ b_hh,
                            const float* __restrict__ values,
                            const float* __restrict__ masks,
                            const float* __restrict__ b_reg)
{
    int idx = blockIdx.x * blockDim.x + threadIdx.x;
    int stride = gridDim.x * blockDim.x;

    for (int i = idx; i < NP * KPB; i += stride) {
        int col = i / KPB, k = i - col * KPB;
        int h = col >> 2, q = col & 3;
        d_wih_h[i] = (h < HID && k < NF)
                   ? __float2half_rn(W_ih[(size_t)(q * HID + h) * LDW + k]) : __half(0.f);
    }
    for (int i = idx; i < NP * KPR; i += stride) {
        int col = i / KPR, k = i - col * KPR;
        int h = col >> 2, q = col & 3;
        d_whh_h[i] = (h < HID && k < HID)
                   ? __float2half_rn(W_hh[(size_t)(q * HID + h) * HID + k]) : __half(0.f);
    }
    for (int i = idx; i < NP; i += stride) {
        int h = i >> 2, q = i & 3;
        if (h < HID) {
            int r = q * HID + h;
            d_wvi[i]   = W_ih[(size_t)r * LDW + VAR];
            d_wmi[i]   = W_ih[(size_t)r * LDW + NF];
            d_bsumi[i] = b_ih[r] + b_hh[r];
        } else {
            d_wvi[i] = 0.f; d_wmi[i] = 0.f; d_bsumi[i] = 0.f;
        }
    }
    for (int i = idx; i < HID; i += stride) {
        float s = 0.f;
        const float* row = W_decay + (size_t)i * NF;
        for (int k = 0; k < NF; k++) s += row[k];
        d_wsum[i] = s;
    }
    for (int i = idx; i < B_ * HID; i += stride) d_c[i] = 0.f;
    for (int i = idx; i < B_ * KPR; i += stride) d_hdech[i] = __half(0.f);
    for (int i = idx; i < B_; i += stride) {
        float xh0 = b_reg[0];                  // h0 = 0 -> x_h = b_reg
        float m0  = masks[i * T_];
        float xr0 = values[(size_t)i * T_ * NF + VAR];
        d_xh[i]    = xh0;
        d_alpha[i] = (1.f - m0) * (xh0 - xr0);
        d_mm[i]    = m0;
    }
}

// ---------------- loss + writeout ------------------------------------------------------
__global__ void loss_kernel(const float* __restrict__ values,
                            const float* __restrict__ masks)
{
    __shared__ float snum[256];
    __shared__ float sden[256];
    const int t = blockIdx.x;
    float num = 0.f, den = 0.f;
    for (int b = threadIdx.x; b < B_; b += 256) {
        float m  = masks[b * T_ + t];
        float xr = values[(size_t)(b * T_ + t) * NF + VAR];
        float xh = d_xh[t * B_ + b];
        num += m * fabsf(xr - xh);
        den += m;
    }
    snum[threadIdx.x] = num;
    sden[threadIdx.x] = den;
    __syncthreads();
    for (int s = 128; s > 0; s >>= 1) {
        if (threadIdx.x < s) {
            snum[threadIdx.x] += snum[threadIdx.x + s];
            sden[threadIdx.x] += sden[threadIdx.x + s];
        }
        __syncthreads();
    }
    if (threadIdx.x == 0) d_steploss[t] = snum[0] / (sden[0] + 1e-5f);
}

__global__ void writeout_kernel(const float* __restrict__ values,
                                const float* __restrict__ masks,
                                float* __restrict__ out, int out_size)
{
    int idx = blockIdx.x * blockDim.x + threadIdx.x;   // over B*T
    const int has_loss = (out_size > B_ * T_) ? 1 : 0;
    if (idx < B_ * T_) {
        int b = idx / T_, t = idx - b * T_;
        float m   = masks[idx];
        float xr  = values[(size_t)idx * NF + VAR];
        float xh  = d_xh[t * B_ + b];
        float imp = m * xr + (1.f - m) * xh;
        int o = has_loss + idx;
        if (o < out_size) out[o] = imp;
    }
    if (idx == 0 && has_loss) {
        float s = 0.f;
        for (int t = 0; t < T_; t++) s += d_steploss[t];
        out[0] = s / (float)T_;
    }
}

// ---------------- launch -----------------------------------------------------------------
extern "C" void kernel_launch(void* const* d_in, const int* in_sizes, int n_in,
                              void* d_out, int out_size)
{
    const float* values  = (const float*)d_in[0];
    const float* masks   = (const float*)d_in[1];
    const float* deltas  = (const float*)d_in[2];
    const float* W_decay = (const float*)d_in[3];
    const float* b_decay = (const float*)d_in[4];
    const float* W_reg   = (const float*)d_in[5];
    const float* b_reg   = (const float*)d_in[6];
    const float* W_ih    = (const float*)d_in[7];
    const float* W_hh    = (const float*)d_in[8];
    const float* b_ih    = (const float*)d_in[9];
    const float* b_hh    = (const float*)d_in[10];
    float* out = (float*)d_out;

    __half *pre_p, *gates_p, *valh_p, *wih_p, *whh_p, *hdech_p;
    cudaGetSymbolAddress((void**)&pre_p,   d_pre);
    cudaGetSymbolAddress((void**)&gates_p, d_gates);
    cudaGetSymbolAddress((void**)&valh_p,  d_valh);
    cudaGetSymbolAddress((void**)&wih_p,   d_wih_h);
    cudaGetSymbolAddress((void**)&whh_p,   d_whh_h);
    cudaGetSymbolAddress((void**)&hdech_p, d_hdech);

    cudaFuncSetAttribute(gemm_hmma, cudaFuncAttributeMaxDynamicSharedMemorySize, SMEM_DYN);

    conv_values_kernel<<<MBT, 256>>>(values);
    prep_kernel<<<4096, 256>>>(W_decay, W_ih, W_hh, b_ih, b_hh, values, masks, b_reg);

    // pre[MBT, NP] = valh @ wih_h^T   (K = 832 -> 26 k-tiles), fp16 out, interleaved cols
    {
        dim3 grid(NP / BN, MBT / BM);
        gemm_hmma<<<grid, 256, SMEM_DYN>>>(valh_p, wih_p, KPB, KPB, KPB / BK, pre_p);
    }

    // recurrence: iteration t = T-1 is dead code (c/h(T-1) unused, xh(T-1) was
    // produced at t = T-2) -> run 19 steps only.
    for (int t = 0; t < T_ - 1; t++) {
        dim3 grid(NP / BN, B_ / BM);
        gemm_hmma<<<grid, 256, SMEM_DYN>>>(hdech_p, whh_p, KPR, KPR, KPR / BK, gates_p);
        lstm_fused_kernel<<<B_, 416>>>(t, values, masks, deltas, b_decay, W_reg, b_reg);
    }

    loss_kernel<<<T_, 256>>>(values, masks);
    writeout_kernel<<<(B_ * T_ + 255) / 256, 256>>>(values, masks, out, out_size);
}